// round 16
// baseline (speedup 1.0000x reference)
#include <cuda_runtime.h>

#define Bb 4
#define Tt 512
#define Cc 128
#define NROWS (Bb * Tt)  // 2048
#define NEG_INF (-1e22f)
#define TI 8

__device__ float g_qT[Cc * NROWS];  // Q transposed
__device__ float g_k[NROWS * Cc];   // K row-major

typedef unsigned long long u64;

// ---- packed f32x2 helpers -------------------------------------------------
__device__ __forceinline__ u64 add2(u64 a, u64 b) {
    u64 s;
    asm("add.rn.f32x2 %0, %1, %2;" : "=l"(s) : "l"(a), "l"(b));
    return s;
}
__device__ __forceinline__ u64 relu2(u64 s) {
    asm("{\n\t"
        ".reg .f32 lo, hi;\n\t"
        "mov.b64 {lo, hi}, %0;\n\t"
        "max.f32 lo, lo, 0f00000000;\n\t"
        "max.f32 hi, hi, 0f00000000;\n\t"
        "mov.b64 %0, {lo, hi};\n\t"
        "}"
        : "+l"(s));
    return s;
}
__device__ __forceinline__ void fma2(u64& acc, u64 a, u64 b) {
    asm("fma.rn.f32x2 %0, %1, %2, %0;" : "+l"(acc) : "l"(a), "l"(b));
}
__device__ __forceinline__ u64 dup2(float w) {
    u64 r;
    asm("mov.b64 %0, {%1, %1};" : "=l"(r) : "f"(w));
    return r;
}

// ---------------------------------------------------------------------------
// Kernel 1: Q/K projection — R4 geometry + fused smem transpose for Q.
// Grid (128, 2): y=0 -> Q (transposed store via smem), y=1 -> K (row-major).
// Block 256 threads: col = tid&127, rh = tid>>7 (8 rows each).
// ---------------------------------------------------------------------------
__global__ void __launch_bounds__(256) qk_kernel(const float* __restrict__ x,
                                                 const float* __restrict__ WQ,
                                                 const float* __restrict__ WK) {
    __shared__ float4 xs[16 * 32];
    __shared__ float  tbuf[16 * 132];  // [row][col] padded, Q path only
    const int tid  = threadIdx.x;
    const int row0 = blockIdx.x * 16;
    const float* W = blockIdx.y ? WK : WQ;

#pragma unroll
    for (int t = 0; t < 2; t++) {
        int f4 = tid + 256 * t;
        int r = f4 >> 5, c = f4 & 31;
        xs[f4] = ((const float4*)(x + (size_t)(row0 + r) * Cc))[c];
    }
    __syncthreads();

    const int col = tid & 127;
    const int rh  = tid >> 7;

    float acc[8];
#pragma unroll
    for (int r = 0; r < 8; r++) acc[r] = 0.f;

#pragma unroll 4
    for (int d4 = 0; d4 < 32; d4++) {
        float w0 = W[(4 * d4 + 0) * Cc + col];
        float w1 = W[(4 * d4 + 1) * Cc + col];
        float w2 = W[(4 * d4 + 2) * Cc + col];
        float w3 = W[(4 * d4 + 3) * Cc + col];
#pragma unroll
        for (int r = 0; r < 8; r++) {
            float4 xv = xs[(rh * 8 + r) * 32 + d4];
            acc[r] += xv.x * w0;
            acc[r] += xv.y * w1;
            acc[r] += xv.z * w2;
            acc[r] += xv.w * w3;
        }
    }

    if (blockIdx.y) {
        // K row-major (coalesced: col consecutive per lane)
#pragma unroll
        for (int r = 0; r < 8; r++)
            g_k[(size_t)(row0 + rh * 8 + r) * Cc + col] = acc[r];
    } else {
        // Q: transpose through smem, then coalesced STG
        __syncthreads();
#pragma unroll
        for (int r = 0; r < 8; r++)
            tbuf[(rh * 8 + r) * 132 + col] = acc[r];  // conflict-free
        __syncthreads();
#pragma unroll
        for (int t = 0; t < 8; t++) {
            int f = tid + 256 * t;  // 0..2047
            int c = f >> 4, rl = f & 15;
            g_qT[(size_t)c * NROWS + row0 + rl] = tbuf[rl * 132 + c];
        }
    }
}

// ---------------------------------------------------------------------------
// Kernel 2: fused score + masked softmax + AV. Grid (64, 4), 512 threads.
// Score/softmax = R11 (measured 34.4us). AV: weights j-major at stride 10
// u64 -> 4 LDS.128 broadcasts per j instead of 8 LDS.64.
// smem (u64): ksd [0,1024) | psd [1024,1152) | sc(float) [1152,3200)
//             scd [3200,8320)  scd[j][10] (8 used; reduce buf reuses scd)
// ---------------------------------------------------------------------------
#define SCD_STRIDE 10
#define AT_SMEM_U64 (3200 + Tt * SCD_STRIDE)
#define AT_SMEM_BYTES (AT_SMEM_U64 * 8)

__global__ void __launch_bounds__(512, 2) attn_kernel(const float* __restrict__ x,
                                                      const float* __restrict__ adj,
                                                      const float* __restrict__ p,
                                                      float* __restrict__ out) {
    extern __shared__ u64 asm_u[];
    u64*   ksd = asm_u;                   // [8][128] k duplicated
    u64*   psd = asm_u + 1024;            // [128]    p duplicated
    float* sc  = (float*)(asm_u + 1152);  // [8][512] raw scores
    u64*   scd = asm_u + 3200;            // [512 j][10] dup'd weights

    const int tid = threadIdx.x;
    const int b   = blockIdx.y;
    const int i0  = blockIdx.x * TI;

    // stage k rows (dup'd) + p (dup'd)
#pragma unroll
    for (int t = 0; t < 2; t++) {
        int idx = tid + 512 * t;  // 0..1023
        int r = idx >> 7, d = idx & 127;
        ksd[r * 128 + d] = dup2(g_k[(size_t)(b * Tt + i0 + r) * Cc + d]);
    }
    if (tid < 128) psd[tid] = dup2(p[tid]);
    __syncthreads();

    // ================= score phase: thread = 2i x 4j, dim pairs (R11) =======
    {
        const int ig = tid >> 7;         // 0..3 -> rows 2ig, 2ig+1
        const int j0 = (tid & 127) * 4;  // 4 consecutive j's
        const float* qb = g_qT + b * Tt + j0;

        u64 a00 = 0, a01 = 0, a10 = 0, a11 = 0;
        const u64* k0p = ksd + (2 * ig + 0) * 128;
        const u64* k1p = ksd + (2 * ig + 1) * 128;

#pragma unroll 4
        for (int d2 = 0; d2 < 64; d2++) {
            const int d = 2 * d2;
            ulonglong2 qa = *(const ulonglong2*)(qb + (size_t)d * NROWS);
            ulonglong2 qc = *(const ulonglong2*)(qb + (size_t)(d + 1) * NROWS);
            ulonglong2 pd = *(const ulonglong2*)(psd + d);
            ulonglong2 k0 = *(const ulonglong2*)(k0p + d);
            ulonglong2 k1 = *(const ulonglong2*)(k1p + d);

            fma2(a00, pd.x, relu2(add2(qa.x, k0.x)));
            fma2(a01, pd.x, relu2(add2(qa.y, k0.x)));
            fma2(a10, pd.x, relu2(add2(qa.x, k1.x)));
            fma2(a11, pd.x, relu2(add2(qa.y, k1.x)));
            fma2(a00, pd.y, relu2(add2(qc.x, k0.y)));
            fma2(a01, pd.y, relu2(add2(qc.y, k0.y)));
            fma2(a10, pd.y, relu2(add2(qc.x, k1.y)));
            fma2(a11, pd.y, relu2(add2(qc.y, k1.y)));
        }
        u64* s0 = (u64*)(sc + (2 * ig + 0) * Tt + j0);
        u64* s1 = (u64*)(sc + (2 * ig + 1) * Tt + j0);
        s0[0] = a00; s0[1] = a01;
        s1[0] = a10; s1[1] = a11;
    }
    __syncthreads();

    // ================= masked softmax (warps 0-7, one row each) =============
    const int warp = tid >> 5, lane = tid & 31;
    if (warp < 8) {
        const int    r    = warp;
        const float* arow = adj + ((size_t)(b * Tt) + i0 + r) * Tt;
        float v[16];
        float m = -3.4e38f;
#pragma unroll
        for (int t = 0; t < 16; t++) {
            int   j = lane + 32 * t;
            float s = sc[r * Tt + j];
            s    = (arow[j] > 0.f) ? s : NEG_INF;
            v[t] = s;
            m    = fmaxf(m, s);
        }
#pragma unroll
        for (int o = 16; o; o >>= 1) m = fmaxf(m, __shfl_xor_sync(0xffffffff, m, o));
        float sum = 0.f;
#pragma unroll
        for (int t = 0; t < 16; t++) {
            v[t] = __expf(v[t] - m);
            sum += v[t];
        }
#pragma unroll
        for (int o = 16; o; o >>= 1) sum += __shfl_xor_sync(0xffffffff, sum, o);
        float inv = 1.f / sum;
#pragma unroll
        for (int t = 0; t < 16; t++)
            scd[(lane + 32 * t) * SCD_STRIDE + r] = dup2(v[t] * inv);
    }
    __syncthreads();

    // ===== AV: warps = 8 jq x 2 dq; weights as 4 LDS.128 broadcasts/j ======
    const int jq = warp >> 1;  // 0..7 -> 64 j's
    const int dq = warp & 1;   // 0/1 -> d half
    const int d0 = dq * 64 + 2 * lane;

    u64 av[8];
#pragma unroll
    for (int i = 0; i < 8; i++) av[i] = 0ull;

    const float* xb = x + (size_t)(b * Tt) * Cc;
#pragma unroll 4
    for (int jj = 0; jj < 64; jj++) {
        int        j   = jq * 64 + jj;
        u64        xv  = *(const u64*)(xb + (size_t)j * Cc + d0);
        ulonglong2 w01 = *(const ulonglong2*)(scd + j * SCD_STRIDE + 0);
        ulonglong2 w23 = *(const ulonglong2*)(scd + j * SCD_STRIDE + 2);
        ulonglong2 w45 = *(const ulonglong2*)(scd + j * SCD_STRIDE + 4);
        ulonglong2 w67 = *(const ulonglong2*)(scd + j * SCD_STRIDE + 6);
        fma2(av[0], w01.x, xv);
        fma2(av[1], w01.y, xv);
        fma2(av[2], w23.x, xv);
        fma2(av[3], w23.y, xv);
        fma2(av[4], w45.x, xv);
        fma2(av[5], w45.y, xv);
        fma2(av[6], w67.x, xv);
        fma2(av[7], w67.y, xv);
    }
    __syncthreads();

    // reduce over jq through smem (reuse scd region: 7*8*64 = 3584 u64)
    u64* buf = scd;
    if (jq != 0) {
#pragma unroll
        for (int i = 0; i < 8; i++)
            buf[((jq - 1) * 8 + i) * 64 + dq * 32 + lane] = av[i];
    }
    __syncthreads();
    if (jq == 0) {
#pragma unroll
        for (int q = 0; q < 7; q++)
#pragma unroll
            for (int i = 0; i < 8; i++)
                av[i] = add2(av[i], buf[(q * 8 + i) * 64 + dq * 32 + lane]);
#pragma unroll
        for (int i = 0; i < 8; i++)
            *(u64*)(out + (size_t)(b * Tt + i0 + i) * Cc + d0) = av[i];
    }
}

// ---------------------------------------------------------------------------
extern "C" void kernel_launch(void* const* d_in, const int* in_sizes, int n_in,
                              void* d_out, int out_size) {
    const float* x   = (const float*)d_in[0];
    const float* adj = (const float*)d_in[1];
    const float* WQ  = (const float*)d_in[2];
    const float* WK  = (const float*)d_in[3];
    const float* p   = (const float*)d_in[4];
    float*       out = (float*)d_out;

    qk_kernel<<<dim3(NROWS / 16, 2), 256>>>(x, WQ, WK);

    cudaFuncSetAttribute(attn_kernel, cudaFuncAttributeMaxDynamicSharedMemorySize,
                         AT_SMEM_BYTES);
    attn_kernel<<<dim3(Tt / TI, Bb), 512, AT_SMEM_BYTES>>>(x, adj, p, out);
}

// round 17
// speedup vs baseline: 1.0499x; 1.0499x over previous
#include <cuda_runtime.h>

#define Bb 4
#define Tt 512
#define Cc 128
#define NROWS (Bb * Tt)  // 2048
#define NEG_INF (-1e22f)
#define TI 16

__device__ float g_q[NROWS * Cc];   // Q row-major
__device__ float g_qT[Cc * NROWS];  // Q transposed
__device__ float g_k[NROWS * Cc];   // K row-major

typedef unsigned long long u64;

// ---- packed f32x2 helpers -------------------------------------------------
__device__ __forceinline__ u64 add2(u64 a, u64 b) {
    u64 s;
    asm("add.rn.f32x2 %0, %1, %2;" : "=l"(s) : "l"(a), "l"(b));
    return s;
}
__device__ __forceinline__ u64 relu2(u64 s) {
    asm("{\n\t"
        ".reg .f32 lo, hi;\n\t"
        "mov.b64 {lo, hi}, %0;\n\t"
        "max.f32 lo, lo, 0f00000000;\n\t"
        "max.f32 hi, hi, 0f00000000;\n\t"
        "mov.b64 %0, {lo, hi};\n\t"
        "}"
        : "+l"(s));
    return s;
}
__device__ __forceinline__ void fma2(u64& acc, u64 a, u64 b) {
    asm("fma.rn.f32x2 %0, %1, %2, %0;" : "+l"(acc) : "l"(a), "l"(b));
}
__device__ __forceinline__ u64 add2r(u64 a, u64 b) { return add2(a, b); }
__device__ __forceinline__ u64 dup2(float w) {
    u64 r;
    asm("mov.b64 %0, {%1, %1};" : "=l"(r) : "f"(w));
    return r;
}
__device__ __forceinline__ float lo2(u64 a) { return __uint_as_float((unsigned)a); }
__device__ __forceinline__ float hi2(u64 a) { return __uint_as_float((unsigned)(a >> 32)); }

// ---------------------------------------------------------------------------
// Kernel 1: Q/K projection — R4 EXACT (row-major outputs, measured 3.6us).
// Grid (128, 2), 256 threads.
// ---------------------------------------------------------------------------
__global__ void __launch_bounds__(256) qk_kernel(const float* __restrict__ x,
                                                 const float* __restrict__ WQ,
                                                 const float* __restrict__ WK) {
    __shared__ float4 xs[16 * 32];
    const int tid  = threadIdx.x;
    const int row0 = blockIdx.x * 16;
    const float* W   = blockIdx.y ? WK : WQ;
    float*       OUT = blockIdx.y ? g_k : g_q;

#pragma unroll
    for (int t = 0; t < 2; t++) {
        int f4 = tid + 256 * t;
        int r = f4 >> 5, c = f4 & 31;
        xs[f4] = ((const float4*)(x + (size_t)(row0 + r) * Cc))[c];
    }
    __syncthreads();

    const int col = tid & 127;
    const int rh  = tid >> 7;

    float acc[8];
#pragma unroll
    for (int r = 0; r < 8; r++) acc[r] = 0.f;

#pragma unroll 4
    for (int d4 = 0; d4 < 32; d4++) {
        float w0 = W[(4 * d4 + 0) * Cc + col];
        float w1 = W[(4 * d4 + 1) * Cc + col];
        float w2 = W[(4 * d4 + 2) * Cc + col];
        float w3 = W[(4 * d4 + 3) * Cc + col];
#pragma unroll
        for (int r = 0; r < 8; r++) {
            float4 xv = xs[(rh * 8 + r) * 32 + d4];
            acc[r] += xv.x * w0;
            acc[r] += xv.y * w1;
            acc[r] += xv.z * w2;
            acc[r] += xv.w * w3;
        }
    }
#pragma unroll
    for (int r = 0; r < 8; r++)
        OUT[(size_t)(row0 + rh * 8 + r) * Cc + col] = acc[r];
}

// ---------------------------------------------------------------------------
// Kernel 1b: transpose g_q -> g_qT. 32x32 tiles. Grid (64, 4), 256 threads.
// ---------------------------------------------------------------------------
__global__ void __launch_bounds__(256) tr_kernel() {
    __shared__ float tile[32 * 33];
    const int tid  = threadIdx.x;
    const int row0 = blockIdx.x * 32;
    const int d0   = blockIdx.y * 32;

#pragma unroll
    for (int t = 0; t < 4; t++) {
        int idx = tid + 256 * t;
        int r = idx >> 5, dl = idx & 31;
        tile[dl * 33 + r] = g_q[(size_t)(row0 + r) * Cc + d0 + dl];
    }
    __syncthreads();
#pragma unroll
    for (int t = 0; t < 4; t++) {
        int idx = tid + 256 * t;
        int dl = idx >> 5, rl = idx & 31;
        g_qT[(size_t)(d0 + dl) * NROWS + row0 + rl] = tile[dl * 33 + rl];
    }
}

// ---------------------------------------------------------------------------
// Kernel 2: fused score + masked softmax + AV. Grid (32, 4) = 128 blocks,
// 512 threads, TI=16. Score: 4 i-groups x 128 j-threads, thread = 4i x 4j
// (q traffic per i-row HALVED vs TI=8/2i design).
// smem (u64): ksd [0,2048) | psd [2048,2176) | sc(float) [2176,6272)
//             scT [6272,15488)  scT[j][18] i-PAIR-packed weights
//             (sc reused as AV reduce buffer)
// ---------------------------------------------------------------------------
#define SCT_STRIDE 18
#define AT_SMEM_U64 (6272 + Tt * SCT_STRIDE)
#define AT_SMEM_BYTES (AT_SMEM_U64 * 8)

__global__ void __launch_bounds__(512, 1) attn_kernel(const float* __restrict__ x,
                                                      const float* __restrict__ adj,
                                                      const float* __restrict__ p,
                                                      float* __restrict__ out) {
    extern __shared__ u64 asm_u[];
    u64*   ksd  = asm_u;                   // [16 i][128 d] k dup'd
    u64*   psd  = asm_u + 2048;            // [128] p dup'd
    float* sc   = (float*)(asm_u + 2176);  // [16][512] raw scores / AV buf
    u64*   scT  = asm_u + 6272;            // [512 j][18] i-pair-packed weights
    float* scTf = (float*)scT;

    const int tid = threadIdx.x;
    const int b   = blockIdx.y;
    const int i0  = blockIdx.x * TI;

    // stage k rows dup'd [i][d] + p dup'd
#pragma unroll
    for (int t = 0; t < 4; t++) {
        int idx = tid + 512 * t;  // 0..2047
        int i = idx >> 7, d = idx & 127;
        ksd[i * 128 + d] = dup2(g_k[(size_t)(b * Tt + i0 + i) * Cc + d]);
    }
    if (tid < 128) psd[tid] = dup2(p[tid]);
    __syncthreads();

    // ================= score: thread = 4i x 4j, dim pairs ==================
    {
        const int ig = tid >> 7;         // 0..3 -> rows 4ig..4ig+3
        const int j0 = (tid & 127) * 4;  // 4 consecutive j's
        const float* qb = g_qT + b * Tt + j0;

        u64 acc[4][2];
#pragma unroll
        for (int m = 0; m < 4; m++) {
            acc[m][0] = 0ull;
            acc[m][1] = 0ull;
        }
        const u64* kb = ksd + (4 * ig) * 128;

#pragma unroll 4
        for (int d2 = 0; d2 < 64; d2++) {
            const int d = 2 * d2;
            ulonglong2 qa = *(const ulonglong2*)(qb + (size_t)d * NROWS);
            ulonglong2 qc = *(const ulonglong2*)(qb + (size_t)(d + 1) * NROWS);
            ulonglong2 pd = *(const ulonglong2*)(psd + d);
            ulonglong2 k0 = *(const ulonglong2*)(kb + 0 * 128 + d);
            ulonglong2 k1 = *(const ulonglong2*)(kb + 1 * 128 + d);
            ulonglong2 k2 = *(const ulonglong2*)(kb + 2 * 128 + d);
            ulonglong2 k3 = *(const ulonglong2*)(kb + 3 * 128 + d);

#define SC_ROW(m, kk)                                      \
    fma2(acc[m][0], pd.x, relu2(add2(qa.x, kk.x)));        \
    fma2(acc[m][1], pd.x, relu2(add2(qa.y, kk.x)));        \
    fma2(acc[m][0], pd.y, relu2(add2(qc.x, kk.y)));        \
    fma2(acc[m][1], pd.y, relu2(add2(qc.y, kk.y)));
            SC_ROW(0, k0)
            SC_ROW(1, k1)
            SC_ROW(2, k2)
            SC_ROW(3, k3)
#undef SC_ROW
        }

#pragma unroll
        for (int m = 0; m < 4; m++) {
            u64* s = (u64*)(sc + (4 * ig + m) * Tt + j0);
            s[0] = acc[m][0];
            s[1] = acc[m][1];
        }
    }
    __syncthreads();

    // ===== masked softmax (16 warps x 1 row); weights stored i-packed ======
    const int warp = tid >> 5, lane = tid & 31;
    {
        const int    r    = warp;  // 0..15
        const float* arow = adj + ((size_t)(b * Tt) + i0 + r) * Tt;
        float v[16];
        float m = -3.4e38f;
#pragma unroll
        for (int t = 0; t < 16; t++) {
            int   j = lane + 32 * t;
            float s = sc[r * Tt + j];
            s    = (arow[j] > 0.f) ? s : NEG_INF;
            v[t] = s;
            m    = fmaxf(m, s);
        }
#pragma unroll
        for (int o = 16; o; o >>= 1) m = fmaxf(m, __shfl_xor_sync(0xffffffff, m, o));
        float sum = 0.f;
#pragma unroll
        for (int t = 0; t < 16; t++) {
            v[t] = __expf(v[t] - m);
            sum += v[t];
        }
#pragma unroll
        for (int o = 16; o; o >>= 1) sum += __shfl_xor_sync(0xffffffff, sum, o);
        float inv = 1.f / sum;
#pragma unroll
        for (int t = 0; t < 16; t++)
            scTf[(lane + 32 * t) * (2 * SCT_STRIDE) + r] = v[t] * inv;
    }
    __syncthreads();

    // ===== AV: 16 warps = 2 ih x 4 jq x 2 dq; thread = 8i(4 pairs) x 2d ====
    // acc packed over i-pairs; x dup'd per dim.
    const int ih = warp >> 3;         // 0/1 -> i rows ih*8 .. ih*8+7
    const int jq = (warp >> 1) & 3;   // 0..3 -> 128 j's
    const int dq = warp & 1;          // 0/1 -> d half
    const int d0 = dq * 64 + 2 * lane;

    u64 av[8];  // [pair c 0..3][dim dd 0..1] -> av[2c+dd]
#pragma unroll
    for (int i = 0; i < 8; i++) av[i] = 0ull;

    const float* xb = x + (size_t)(b * Tt) * Cc + d0;
#pragma unroll 4
    for (int jj = 0; jj < 128; jj++) {
        const int  j   = jq * 128 + jj;
        u64        xv  = *(const u64*)(xb + (size_t)j * Cc);
        ulonglong2 w01 = *(const ulonglong2*)(scT + j * SCT_STRIDE + ih * 4);
        ulonglong2 w23 = *(const ulonglong2*)(scT + j * SCT_STRIDE + ih * 4 + 2);
        u64 xlo = dup2(lo2(xv));
        u64 xhi = dup2(hi2(xv));
        fma2(av[0], w01.x, xlo);
        fma2(av[1], w01.x, xhi);
        fma2(av[2], w01.y, xlo);
        fma2(av[3], w01.y, xhi);
        fma2(av[4], w23.x, xlo);
        fma2(av[5], w23.x, xhi);
        fma2(av[6], w23.y, xlo);
        fma2(av[7], w23.y, xhi);
    }
    __syncthreads();

    // reduce over jq through smem (reuse sc region: 12 slots x 256 u64 = 24KB)
    u64* buf = (u64*)sc;
    if (jq != 0) {
        const int slot = (jq - 1) * 4 + ih * 2 + dq;  // 0..11
#pragma unroll
        for (int k = 0; k < 8; k++) buf[slot * 256 + lane * 8 + k] = av[k];
    }
    __syncthreads();
    if (jq == 0) {
#pragma unroll
        for (int q = 0; q < 3; q++) {
            const int slot = q * 4 + ih * 2 + dq;
#pragma unroll
            for (int k = 0; k < 8; k++)
                av[k] = add2r(av[k], buf[slot * 256 + lane * 8 + k]);
        }
        // store: av[2c+dd] holds rows (ih*8+2c, ih*8+2c+1) at dim d0+dd
#pragma unroll
        for (int c = 0; c < 4; c++) {
#pragma unroll
            for (int dd = 0; dd < 2; dd++) {
                u64 a = av[2 * c + dd];
                out[(size_t)(b * Tt + i0 + ih * 8 + 2 * c + 0) * Cc + d0 + dd] = lo2(a);
                out[(size_t)(b * Tt + i0 + ih * 8 + 2 * c + 1) * Cc + d0 + dd] = hi2(a);
            }
        }
    }
}

// ---------------------------------------------------------------------------
extern "C" void kernel_launch(void* const* d_in, const int* in_sizes, int n_in,
                              void* d_out, int out_size) {
    const float* x   = (const float*)d_in[0];
    const float* adj = (const float*)d_in[1];
    const float* WQ  = (const float*)d_in[2];
    const float* WK  = (const float*)d_in[3];
    const float* p   = (const float*)d_in[4];
    float*       out = (float*)d_out;

    qk_kernel<<<dim3(NROWS / 16, 2), 256>>>(x, WQ, WK);
    tr_kernel<<<dim3(NROWS / 32, Cc / 32), 256>>>();

    cudaFuncSetAttribute(attn_kernel, cudaFuncAttributeMaxDynamicSharedMemorySize,
                         AT_SMEM_BYTES);
    attn_kernel<<<dim3(Tt / TI, Bb), 512, AT_SMEM_BYTES>>>(x, adj, p, out);
}